// round 1
// baseline (speedup 1.0000x reference)
#include <cuda_runtime.h>
#include <cuda_bf16.h>
#include <cstdint>

// Problem constants (fixed shapes from reference)
#define PB 4
#define PT 2048
#define PD 1024
#define PH 16
#define PDH 64
#define PM (PB*PT)          // 8192 rows
#define PN 1024             // H*Dh == D
#define PK 1024

// ---------------- scratch (device globals; no allocations allowed) ----------
__device__ float g_Q [PM*PN];
__device__ float g_K [PM*PN];
__device__ float g_V [PM*PN];
__device__ float g_OH[PM*PN];
__device__ float g_WOt[PD*PN];

// ---------------- WO transpose: [H][D][Dh] -> [D][H*Dh] ---------------------
__global__ void transpose_wo(const float* __restrict__ WO, float* __restrict__ WOt) {
    int idx = blockIdx.x * 256 + threadIdx.x;     // H*D*Dh = 1,048,576 threads
    int k = idx & 63;
    int d = (idx >> 6) & 1023;
    int h = idx >> 16;
    WOt[d * 1024 + h * 64 + k] = WO[idx];
}

// ---------------- NT GEMM + bias: C[m][n] = sum_k A[m][k]*B[n][k] + bias[n] -
// M=8192, N=1024, K=1024 fixed. 128x128 block tile, BK=16, 8x8 per thread.
__global__ __launch_bounds__(256)
void gemm_nt_bias(const float* __restrict__ A, const float* __restrict__ B,
                  const float* __restrict__ bias, float* __restrict__ C) {
    __shared__ float As[16][132];   // transposed tiles: As[k][m]
    __shared__ float Bs[16][132];

    const int tid = threadIdx.x;
    const int tx = tid & 15, ty = tid >> 4;
    const float* Ag = A + (size_t)blockIdx.y * 128 * PK;
    const float* Bg = B + (size_t)blockIdx.x * 128 * PK;

    const int lr = tid >> 1;           // 0..127
    const int lc = (tid & 1) * 8;      // 0 or 8

    float acc[8][8];
#pragma unroll
    for (int i = 0; i < 8; i++)
#pragma unroll
        for (int j = 0; j < 8; j++) acc[i][j] = 0.f;

    for (int k0 = 0; k0 < PK; k0 += 16) {
        float4 a0 = *(const float4*)(Ag + (size_t)lr * PK + k0 + lc);
        float4 a1 = *(const float4*)(Ag + (size_t)lr * PK + k0 + lc + 4);
        float4 b0 = *(const float4*)(Bg + (size_t)lr * PK + k0 + lc);
        float4 b1 = *(const float4*)(Bg + (size_t)lr * PK + k0 + lc + 4);
        __syncthreads();   // previous compute done before overwriting tiles
        As[lc+0][lr] = a0.x; As[lc+1][lr] = a0.y; As[lc+2][lr] = a0.z; As[lc+3][lr] = a0.w;
        As[lc+4][lr] = a1.x; As[lc+5][lr] = a1.y; As[lc+6][lr] = a1.z; As[lc+7][lr] = a1.w;
        Bs[lc+0][lr] = b0.x; Bs[lc+1][lr] = b0.y; Bs[lc+2][lr] = b0.z; Bs[lc+3][lr] = b0.w;
        Bs[lc+4][lr] = b1.x; Bs[lc+5][lr] = b1.y; Bs[lc+6][lr] = b1.z; Bs[lc+7][lr] = b1.w;
        __syncthreads();
#pragma unroll
        for (int kk = 0; kk < 16; kk++) {
            float ra[8], rb[8];
            *(float4*)&ra[0] = *(const float4*)&As[kk][4 * ty];
            *(float4*)&ra[4] = *(const float4*)&As[kk][64 + 4 * ty];
            *(float4*)&rb[0] = *(const float4*)&Bs[kk][4 * tx];
            *(float4*)&rb[4] = *(const float4*)&Bs[kk][64 + 4 * tx];
#pragma unroll
            for (int i = 0; i < 8; i++)
#pragma unroll
                for (int j = 0; j < 8; j++) acc[i][j] += ra[i] * rb[j];
        }
    }

    const int row0 = blockIdx.y * 128;
    const int col0 = blockIdx.x * 128;
    float4 bia = *(const float4*)(bias + col0 + 4 * tx);
    float4 bib = *(const float4*)(bias + col0 + 64 + 4 * tx);
#pragma unroll
    for (int i = 0; i < 8; i++) {
        int r = row0 + ((i < 4) ? (4 * ty + i) : (64 + 4 * ty + (i - 4)));
        float4 v0 = make_float4(acc[i][0] + bia.x, acc[i][1] + bia.y,
                                acc[i][2] + bia.z, acc[i][3] + bia.w);
        float4 v1 = make_float4(acc[i][4] + bib.x, acc[i][5] + bib.y,
                                acc[i][6] + bib.z, acc[i][7] + bib.w);
        *(float4*)(C + (size_t)r * PN + col0 + 4 * tx)      = v0;
        *(float4*)(C + (size_t)r * PN + col0 + 64 + 4 * tx) = v1;
    }
}

// ---------------- flash attention: per (b,h), 64-query x 64-key tiles -------
// Q/K/V/OH are [8192][1024] with column offset h*64 (layout [B,T,H,Dh]).
#define LDP 68
__global__ __launch_bounds__(256)
void flash_kernel(const float* __restrict__ Qg, const float* __restrict__ Kg,
                  const float* __restrict__ Vg, float* __restrict__ OHg) {
    extern __shared__ float sm[];
    float* Qt  = sm;               // [64][LDP]  transposed: Qt[k][r]
    float* KPt = sm + 64 * LDP;    // K transposed [k][c], reused as P^T [c][r]
    float* Vs  = sm + 2 * 64 * LDP; // [c][LDP]  natural

    const int tid = threadIdx.x;
    const int tx = tid & 15, ty = tid >> 4;
    const int q0 = blockIdx.x * 64;
    const int bh = blockIdx.y;
    const int b = bh >> 4, h = bh & 15;
    const size_t base = (size_t)b * (PT * PN) + (size_t)h * PDH;

    const int lr  = tid >> 2;       // 0..63
    const int lc4 = tid & 3;        // float4 slot base

    // load Q tile transposed, pre-scaled by 1/sqrt(Dh)
#pragma unroll
    for (int u = 0; u < 4; u++) {
        int c = (lc4 + 4 * u) * 4;
        float4 v = *(const float4*)(Qg + base + (size_t)(q0 + lr) * PN + c);
        Qt[(c + 0) * LDP + lr] = v.x * 0.125f;
        Qt[(c + 1) * LDP + lr] = v.y * 0.125f;
        Qt[(c + 2) * LDP + lr] = v.z * 0.125f;
        Qt[(c + 3) * LDP + lr] = v.w * 0.125f;
    }

    float m_r[4], l_r[4], o[4][4];
#pragma unroll
    for (int i = 0; i < 4; i++) {
        m_r[i] = -1e30f; l_r[i] = 0.f;
#pragma unroll
        for (int j = 0; j < 4; j++) o[i][j] = 0.f;
    }

    for (int c0 = 0; c0 < PT; c0 += 64) {
        __syncthreads();   // previous PV done (and Q-store visible on iter 0)
#pragma unroll
        for (int u = 0; u < 4; u++) {
            int c = (lc4 + 4 * u) * 4;
            float4 kv = *(const float4*)(Kg + base + (size_t)(c0 + lr) * PN + c);
            KPt[(c + 0) * LDP + lr] = kv.x;
            KPt[(c + 1) * LDP + lr] = kv.y;
            KPt[(c + 2) * LDP + lr] = kv.z;
            KPt[(c + 3) * LDP + lr] = kv.w;
            float4 vv = *(const float4*)(Vg + base + (size_t)(c0 + lr) * PN + c);
            *(float4*)&Vs[lr * LDP + c] = vv;
        }
        __syncthreads();

        // S tile: s[i][j] = sum_k Qt[k][4ty+i] * KPt[k][4tx+j]
        float s[4][4];
#pragma unroll
        for (int i = 0; i < 4; i++)
#pragma unroll
            for (int j = 0; j < 4; j++) s[i][j] = 0.f;
#pragma unroll
        for (int kk = 0; kk < 64; kk++) {
            float4 qa = *(const float4*)&Qt[kk * LDP + 4 * ty];
            float4 kb = *(const float4*)&KPt[kk * LDP + 4 * tx];
            s[0][0] += qa.x*kb.x; s[0][1] += qa.x*kb.y; s[0][2] += qa.x*kb.z; s[0][3] += qa.x*kb.w;
            s[1][0] += qa.y*kb.x; s[1][1] += qa.y*kb.y; s[1][2] += qa.y*kb.z; s[1][3] += qa.y*kb.w;
            s[2][0] += qa.z*kb.x; s[2][1] += qa.z*kb.y; s[2][2] += qa.z*kb.z; s[2][3] += qa.z*kb.w;
            s[3][0] += qa.w*kb.x; s[3][1] += qa.w*kb.y; s[3][2] += qa.w*kb.z; s[3][3] += qa.w*kb.w;
        }

        // online softmax (rows 4ty+i; 16-lane row groups share stats via shfl)
#pragma unroll
        for (int i = 0; i < 4; i++) {
            float rm = fmaxf(fmaxf(s[i][0], s[i][1]), fmaxf(s[i][2], s[i][3]));
            rm = fmaxf(rm, __shfl_xor_sync(0xffffffffu, rm, 8));
            rm = fmaxf(rm, __shfl_xor_sync(0xffffffffu, rm, 4));
            rm = fmaxf(rm, __shfl_xor_sync(0xffffffffu, rm, 2));
            rm = fmaxf(rm, __shfl_xor_sync(0xffffffffu, rm, 1));
            float mnew = fmaxf(m_r[i], rm);
            float a = __expf(m_r[i] - mnew);
            float rs = 0.f;
#pragma unroll
            for (int j = 0; j < 4; j++) { s[i][j] = __expf(s[i][j] - mnew); rs += s[i][j]; }
            rs += __shfl_xor_sync(0xffffffffu, rs, 8);
            rs += __shfl_xor_sync(0xffffffffu, rs, 4);
            rs += __shfl_xor_sync(0xffffffffu, rs, 2);
            rs += __shfl_xor_sync(0xffffffffu, rs, 1);
            l_r[i] = a * l_r[i] + rs;
            m_r[i] = mnew;
#pragma unroll
            for (int j = 0; j < 4; j++) o[i][j] *= a;
        }

        __syncthreads();  // all S reads of KPt done before overwriting with P^T
#pragma unroll
        for (int j = 0; j < 4; j++) {
            *(float4*)&KPt[(4 * tx + j) * LDP + 4 * ty] =
                make_float4(s[0][j], s[1][j], s[2][j], s[3][j]);
        }
        __syncthreads();

        // O += P * V : o[i][j] += Pt[c][4ty+i] * Vs[c][4tx+j]
#pragma unroll
        for (int c = 0; c < 64; c++) {
            float4 pp = *(const float4*)&KPt[c * LDP + 4 * ty];
            float4 vv = *(const float4*)&Vs[c * LDP + 4 * tx];
            o[0][0] += pp.x*vv.x; o[0][1] += pp.x*vv.y; o[0][2] += pp.x*vv.z; o[0][3] += pp.x*vv.w;
            o[1][0] += pp.y*vv.x; o[1][1] += pp.y*vv.y; o[1][2] += pp.y*vv.z; o[1][3] += pp.y*vv.w;
            o[2][0] += pp.z*vv.x; o[2][1] += pp.z*vv.y; o[2][2] += pp.z*vv.z; o[2][3] += pp.z*vv.w;
            o[3][0] += pp.w*vv.x; o[3][1] += pp.w*vv.y; o[3][2] += pp.w*vv.z; o[3][3] += pp.w*vv.w;
        }
    }

    // epilogue: O /= l, write [B,T,H,Dh]
#pragma unroll
    for (int i = 0; i < 4; i++) {
        float inv = 1.f / l_r[i];
        float4 w = make_float4(o[i][0] * inv, o[i][1] * inv, o[i][2] * inv, o[i][3] * inv);
        *(float4*)(OHg + base + (size_t)(q0 + 4 * ty + i) * PN + 4 * tx) = w;
    }
}

// ---------------- launch -----------------------------------------------------
extern "C" void kernel_launch(void* const* d_in, const int* in_sizes, int n_in,
                              void* d_out, int out_size) {
    const float* x  = (const float*)d_in[0];
    const float* WQ = (const float*)d_in[1];
    const float* bQ = (const float*)d_in[2];
    const float* WK = (const float*)d_in[3];
    const float* bK = (const float*)d_in[4];
    const float* WV = (const float*)d_in[5];
    const float* bV = (const float*)d_in[6];
    const float* WO = (const float*)d_in[7];
    const float* bO = (const float*)d_in[8];
    float* out = (float*)d_out;

    float *Q, *K, *V, *OH, *WOt;
    cudaGetSymbolAddress((void**)&Q,   g_Q);
    cudaGetSymbolAddress((void**)&K,   g_K);
    cudaGetSymbolAddress((void**)&V,   g_V);
    cudaGetSymbolAddress((void**)&OH,  g_OH);
    cudaGetSymbolAddress((void**)&WOt, g_WOt);

    const int flash_smem = 3 * 64 * LDP * (int)sizeof(float);  // 52224 B
    cudaFuncSetAttribute(flash_kernel, cudaFuncAttributeMaxDynamicSharedMemorySize,
                         flash_smem);

    dim3 gg(PN / 128, PM / 128);   // (8, 64)
    transpose_wo<<<(PD * PN) / 256, 256>>>(WO, WOt);
    gemm_nt_bias<<<gg, 256>>>(x, WQ, bQ, Q);
    gemm_nt_bias<<<gg, 256>>>(x, WK, bK, K);
    gemm_nt_bias<<<gg, 256>>>(x, WV, bV, V);
    flash_kernel<<<dim3(PT / 64, PB * PH), 256, flash_smem>>>(Q, K, V, OH);
    gemm_nt_bias<<<gg, 256>>>(OH, WOt, bO, out);
}